// round 9
// baseline (speedup 1.0000x reference)
#include <cuda_runtime.h>
#include <cuda_bf16.h>
#include <cstdint>
#include <math.h>

#define BB 8
#define SS 1024
#define DD 1024
#define NH 16
#define HH 64
#define MROWS (BB*SS)            // 8192
#define Y_SIZE (BB*SS*DD)        // 8388608

// ---------------------------------------------------------------------------
// Scratch (device globals; no allocations allowed)
// ---------------------------------------------------------------------------
__device__ float g_ypre[MROWS*DD];                         // pre-layernorm y
__device__ __nv_bfloat16 g_xhi[MROWS*DD], g_xlo[MROWS*DD]; // x split
__device__ __nv_bfloat16 g_wThi[DD*DD], g_wTlo[DD*DD];     // proj B: [c=n*64+h][d]
__device__ __nv_bfloat16 g_lwhi[DD*DD], g_lwlo[DD*DD];     // outproj B: [d][k]
__device__ __nv_bfloat16 g_lhi[MROWS*DD], g_llo[MROWS*DD]; // logits split [r][n*64+h]
__device__ __nv_bfloat16 g_ohhi[MROWS*DD], g_ohlo[MROWS*DD]; // attn heads out split

// ---------------------------------------------------------------------------
// mma.sync / ldmatrix / cp.async helpers (base ISA)
// ---------------------------------------------------------------------------
__device__ __forceinline__ uint32_t smem_u32(const void* p) {
    uint32_t a;
    asm("{ .reg .u64 t; cvta.to.shared.u64 t, %1; cvt.u32.u64 %0, t; }" : "=r"(a) : "l"(p));
    return a;
}

__device__ __forceinline__ void mma_bf16(float c[4],
                                         unsigned a0, unsigned a1, unsigned a2, unsigned a3,
                                         unsigned b0, unsigned b1) {
    asm volatile("mma.sync.aligned.m16n8k16.row.col.f32.bf16.bf16.f32 "
        "{%0,%1,%2,%3}, {%4,%5,%6,%7}, {%8,%9}, {%0,%1,%2,%3};"
        : "+f"(c[0]), "+f"(c[1]), "+f"(c[2]), "+f"(c[3])
        : "r"(a0), "r"(a1), "r"(a2), "r"(a3), "r"(b0), "r"(b1));
}

__device__ __forceinline__ void ldsm4(unsigned r[4], uint32_t addr) {
    asm volatile("ldmatrix.sync.aligned.m8n8.x4.shared.b16 {%0,%1,%2,%3}, [%4];"
        : "=r"(r[0]), "=r"(r[1]), "=r"(r[2]), "=r"(r[3]) : "r"(addr));
}
__device__ __forceinline__ void ldsm2(unsigned r[2], uint32_t addr) {
    asm volatile("ldmatrix.sync.aligned.m8n8.x2.shared.b16 {%0,%1}, [%2];"
        : "=r"(r[0]), "=r"(r[1]) : "r"(addr));
}
__device__ __forceinline__ void ldsm2t(unsigned r[2], uint32_t addr) {
    asm volatile("ldmatrix.sync.aligned.m8n8.x2.trans.shared.b16 {%0,%1}, [%2];"
        : "=r"(r[0]), "=r"(r[1]) : "r"(addr));
}

__device__ __forceinline__ void cp16(uint32_t dst, const void* src) {
    asm volatile("cp.async.cg.shared.global [%0], [%1], 16;" :: "r"(dst), "l"(src));
}
#define CP_COMMIT() asm volatile("cp.async.commit_group;" ::: "memory")
#define CP_WAIT1()  asm volatile("cp.async.wait_group 1;" ::: "memory")
#define CP_WAIT0()  asm volatile("cp.async.wait_group 0;" ::: "memory")

// hi/lo split of float pair -> two packed bf16x2 regs
__device__ __forceinline__ void split2(float x, float y, unsigned& h, unsigned& l) {
    __nv_bfloat16 hx = __float2bfloat16(x), hy = __float2bfloat16(y);
    __nv_bfloat162 hp(hx, hy);
    __nv_bfloat162 lp(__float2bfloat16(x - __bfloat162float(hx)),
                      __float2bfloat16(y - __bfloat162float(hy)));
    h = *(unsigned*)&hp;
    l = *(unsigned*)&lp;
}

// ---------------------------------------------------------------------------
// Converters: fp32 -> bf16 hi/lo split
// ---------------------------------------------------------------------------
__global__ __launch_bounds__(256) void split4_kernel(const float* __restrict__ s,
                                                     __nv_bfloat16* __restrict__ hi,
                                                     __nv_bfloat16* __restrict__ lo, int n4) {
    int i = blockIdx.x * 256 + threadIdx.x;
    if (i >= n4) return;
    float4 v = ((const float4*)s)[i];
    unsigned h0, l0, h1, l1;
    split2(v.x, v.y, h0, l0);
    split2(v.z, v.w, h1, l1);
    ((unsigned*)hi)[i*2]   = h0;
    ((unsigned*)hi)[i*2+1] = h1;
    ((unsigned*)lo)[i*2]   = l0;
    ((unsigned*)lo)[i*2+1] = l1;
}

// w [NH][DD][HH] -> wT[c=n*64+h][d], split hi/lo
__global__ __launch_bounds__(256) void convw_kernel(const float* __restrict__ w) {
    int o = blockIdx.x * 256 + threadIdx.x;
    int c = o >> 10, d = o & 1023;
    int n = c >> 6, h = c & 63;
    float v = __ldg(&w[(n * 1024 + d) * 64 + h]);
    __nv_bfloat16 hv = __float2bfloat16(v);
    g_wThi[o] = hv;
    g_wTlo[o] = __float2bfloat16(v - __bfloat162float(hv));
}

// ---------------------------------------------------------------------------
// Dense GEMM via mma.sync, cp.async double-buffered, K-chunk 32.
// Smem/CTA = 80KB -> 2 CTAs/SM (16 warps). Block 128x128, 8 warps (2m x 4n),
// warp tile 64x32. Smem row stride 40 bf16 (80B, ldsm conflict-free).
// EPI 0: C as bf16 hi/lo. EPI 1: fp32 C = acc + RX + BIAS.
// ---------------------------------------------------------------------------
#define GP_AH 0
#define GP_AL 10240
#define GP_BH 20480
#define GP_BL 30720
#define GBUF  40960
#define GSMEM (2*GBUF)    // 81920

template<int EPI>
__global__ __launch_bounds__(256) void gemm_mma(
    const __nv_bfloat16* __restrict__ Ah, const __nv_bfloat16* __restrict__ Al,
    const __nv_bfloat16* __restrict__ Bh, const __nv_bfloat16* __restrict__ Bl,
    __nv_bfloat16* __restrict__ Chi, __nv_bfloat16* __restrict__ Clo,
    float* __restrict__ Cf, const float* __restrict__ RX, const float* __restrict__ BIAS)
{
    extern __shared__ char sm[];
    const uint32_t sb = smem_u32(sm);
    const int tid = threadIdx.x, w = tid >> 5, lane = tid & 31;
    const int wm = w >> 2, wn = w & 3;
    const int r0 = blockIdx.x * 128, c0 = blockIdx.y * 128;
    const int lrow = tid >> 2, lc4 = tid & 3;     // 64 rows x 4 col-chunks

    float acc[4][4][4] = {};

    auto load_chunk = [&](int buf, int k0) {
        const uint32_t bb = sb + buf * GBUF;
        #pragma unroll
        for (int it = 0; it < 2; it++) {
            int rr = lrow + it * 64;
            size_t goA = (size_t)(r0 + rr) * 1024 + k0 + lc4 * 8;
            size_t goB = (size_t)(c0 + rr) * 1024 + k0 + lc4 * 8;
            uint32_t so = rr * 80 + lc4 * 16;
            cp16(bb + GP_AH + so, Ah + goA);
            cp16(bb + GP_AL + so, Al + goA);
            cp16(bb + GP_BH + so, Bh + goB);
            cp16(bb + GP_BL + so, Bl + goB);
        }
    };

    load_chunk(0, 0);
    CP_COMMIT();

    #pragma unroll 1
    for (int ch = 0; ch < 32; ch++) {
        if (ch < 31) {
            load_chunk((ch + 1) & 1, (ch + 1) * 32);
            CP_COMMIT();
            CP_WAIT1();
        } else {
            CP_WAIT0();
        }
        __syncthreads();
        const uint32_t bb = sb + (ch & 1) * GBUF;
        #pragma unroll
        for (int ks = 0; ks < 2; ks++) {
            unsigned ah[4][4], al[4][4], bh[2][4], bl[2][4];
            uint32_t abase = bb + (wm * 64 + (lane & 15)) * 80 + ks * 32 + (lane >> 4) * 16;
            #pragma unroll
            for (int mi = 0; mi < 4; mi++) {
                ldsm4(ah[mi], abase + GP_AH + mi * 1280);
                ldsm4(al[mi], abase + GP_AL + mi * 1280);
            }
            uint32_t bbase = bb + (wn * 32 + (lane & 15)) * 80 + ks * 32 + (lane >> 4) * 16;
            #pragma unroll
            for (int ni = 0; ni < 2; ni++) {
                ldsm4(bh[ni], bbase + GP_BH + ni * 1280);
                ldsm4(bl[ni], bbase + GP_BL + ni * 1280);
            }
            #pragma unroll
            for (int mi = 0; mi < 4; mi++)
                #pragma unroll
                for (int ni = 0; ni < 2; ni++) {
                    mma_bf16(acc[mi][2*ni],   ah[mi][0],ah[mi][1],ah[mi][2],ah[mi][3], bh[ni][0], bh[ni][2]);
                    mma_bf16(acc[mi][2*ni+1], ah[mi][0],ah[mi][1],ah[mi][2],ah[mi][3], bh[ni][1], bh[ni][3]);
                    mma_bf16(acc[mi][2*ni],   ah[mi][0],ah[mi][1],ah[mi][2],ah[mi][3], bl[ni][0], bl[ni][2]);
                    mma_bf16(acc[mi][2*ni+1], ah[mi][0],ah[mi][1],ah[mi][2],ah[mi][3], bl[ni][1], bl[ni][3]);
                    mma_bf16(acc[mi][2*ni],   al[mi][0],al[mi][1],al[mi][2],al[mi][3], bh[ni][0], bh[ni][2]);
                    mma_bf16(acc[mi][2*ni+1], al[mi][0],al[mi][1],al[mi][2],al[mi][3], bh[ni][1], bh[ni][3]);
                }
        }
        __syncthreads();
    }

    // epilogue
    #pragma unroll
    for (int mi = 0; mi < 4; mi++) {
        int rr = r0 + wm * 64 + mi * 16 + (lane >> 2);
        #pragma unroll
        for (int nj = 0; nj < 4; nj++) {
            int cc = c0 + wn * 32 + nj * 8 + 2 * (lane & 3);
            if (EPI == 0) {
                #pragma unroll
                for (int half = 0; half < 2; half++) {
                    unsigned h, l;
                    split2(acc[mi][nj][half*2], acc[mi][nj][half*2+1], h, l);
                    size_t go = (size_t)(rr + half*8) * 1024 + cc;
                    *(unsigned*)(Chi + go) = h;
                    *(unsigned*)(Clo + go) = l;
                }
            } else {
                #pragma unroll
                for (int half = 0; half < 2; half++) {
                    size_t go = (size_t)(rr + half*8) * 1024 + cc;
                    float2 xv = *(const float2*)(RX + go);
                    float2 bv = *(const float2*)(BIAS + cc);
                    float2 o;
                    o.x = acc[mi][nj][half*2]   + xv.x + bv.x;
                    o.y = acc[mi][nj][half*2+1] + xv.y + bv.y;
                    *(float2*)(Cf + go) = o;
                }
            }
        }
    }
}

// ---------------------------------------------------------------------------
// Fused attention per (n, b, 32-row tile): 512 threads (16 warps).
// QK^T warp tile 32q x 8k; PV warp tile 16q x 8h. Q frags hoisted to regs.
// scores stride 1032 fp32. KV cp.async double-buffered.
// ---------------------------------------------------------------------------
#define SCSTR 1032
#define A_QH  132096                    // 32*144 = 4608
#define A_QL  136704
#define A_KB  141312                    // 2 bufs x (KH 18432 + KL 18432)
#define A_KBUF 36864
#define ASMEM (A_KB + 2*A_KBUF)         // 215040

__global__ __launch_bounds__(512) void attn_kernel(
    const __nv_bfloat16* __restrict__ LHI, const __nv_bfloat16* __restrict__ LLO,
    float* __restrict__ out_attn,
    __nv_bfloat16* __restrict__ OHI, __nv_bfloat16* __restrict__ OLO)
{
    extern __shared__ char sm[];
    const uint32_t sb = smem_u32(sm);
    float* scores = (float*)sm;
    __shared__ float rs[32];

    const int rt = blockIdx.x, b = blockIdx.y, n = blockIdx.z;
    const int s0 = rt * 32;
    const int tid = threadIdx.x, w = tid >> 5, lane = tid & 31;
    const size_t rowbase = (size_t)b * 1024;
    const int colbase = n * 64;

    auto load_kv = [&](int buf, int tile) {
        const uint32_t bh = sb + A_KB + buf * A_KBUF;
        #pragma unroll
        for (int it = 0; it < 2; it++) {
            int row = (tid >> 3) + it * 64;
            size_t go = (rowbase + tile * 128 + row) * 1024 + colbase + (tid & 7) * 8;
            uint32_t so = row * 144 + (tid & 7) * 16;
            cp16(bh + so,         LHI + go);
            cp16(bh + 18432 + so, LLO + go);
        }
    };

    // prefetch K tile 0; load Q tile (32 x 64) hi/lo direct
    load_kv(0, 0);
    CP_COMMIT();
    if (tid < 256) {
        int row = tid >> 3, c8 = tid & 7;
        uint32_t so = row * 144 + c8 * 16;
        size_t go = (rowbase + s0 + row) * 1024 + colbase + c8 * 8;
        *(uint4*)(sm + A_QH + so) = *(const uint4*)(LHI + go);
        *(uint4*)(sm + A_QL + so) = *(const uint4*)(LLO + go);
    }
    __syncthreads();

    // hoist Q fragments (kt-invariant): [ks][mi][4] hi+lo
    unsigned qh[4][2][4], ql[4][2][4];
    #pragma unroll
    for (int ks = 0; ks < 4; ks++) {
        uint32_t qb = sb + (lane & 15) * 144 + ks * 32 + (lane >> 4) * 16;
        #pragma unroll
        for (int mi = 0; mi < 2; mi++) {
            ldsm4(qh[ks][mi], qb + A_QH + mi * 2304);
            ldsm4(ql[ks][mi], qb + A_QL + mi * 2304);
        }
    }

    const float scale = 0.125f;
    // ---- QK^T: 8 key tiles of 128, dbuf; warp w -> keys [w*8, w*8+8) ----
    #pragma unroll 1
    for (int kt = 0; kt < 8; kt++) {
        if (kt < 7) {
            load_kv((kt + 1) & 1, kt + 1);
            CP_COMMIT();
            CP_WAIT1();
        } else {
            CP_WAIT0();
        }
        __syncthreads();
        const uint32_t kbase = sb + A_KB + (kt & 1) * A_KBUF;

        float sqk[2][4] = {};
        #pragma unroll
        for (int ks = 0; ks < 4; ks++) {
            unsigned kh2[2], kl2[2];
            uint32_t kb = kbase + (w * 8 + (lane & 7)) * 144 + ks * 32 + ((lane >> 3) & 1) * 16;
            ldsm2(kh2, kb);
            ldsm2(kl2, kb + 18432);
            #pragma unroll
            for (int mi = 0; mi < 2; mi++) {
                mma_bf16(sqk[mi], qh[ks][mi][0],qh[ks][mi][1],qh[ks][mi][2],qh[ks][mi][3], kh2[0], kh2[1]);
                mma_bf16(sqk[mi], qh[ks][mi][0],qh[ks][mi][1],qh[ks][mi][2],qh[ks][mi][3], kl2[0], kl2[1]);
                mma_bf16(sqk[mi], ql[ks][mi][0],ql[ks][mi][1],ql[ks][mi][2],ql[ks][mi][3], kh2[0], kh2[1]);
            }
        }
        #pragma unroll
        for (int mi = 0; mi < 2; mi++) {
            int sr = mi * 16 + (lane >> 2);
            int cc = kt * 128 + w * 8 + 2 * (lane & 3);
            *(float2*)&scores[sr * SCSTR + cc] =
                make_float2(sqk[mi][0] * scale, sqk[mi][1] * scale);
            *(float2*)&scores[(sr + 8) * SCSTR + cc] =
                make_float2(sqk[mi][2] * scale, sqk[mi][3] * scale);
        }
        __syncthreads();
    }

    // ---- softmax (fp32 exact): row = tid/16, 16 threads per row ----
    {
        const int row = tid >> 4, c = tid & 15;
        float* srow = scores + row * SCSTR;
        float m = -1e30f;
        #pragma unroll 8
        for (int i = 0; i < 64; i++) m = fmaxf(m, srow[c + 16 * i]);
        m = fmaxf(m, __shfl_xor_sync(0xffffffffu, m, 1));
        m = fmaxf(m, __shfl_xor_sync(0xffffffffu, m, 2));
        m = fmaxf(m, __shfl_xor_sync(0xffffffffu, m, 4));
        m = fmaxf(m, __shfl_xor_sync(0xffffffffu, m, 8));
        float sum = 0.f;
        #pragma unroll 8
        for (int i = 0; i < 64; i++) {
            float e = __expf(srow[c + 16 * i] - m);
            srow[c + 16 * i] = e;
            sum += e;
        }
        sum += __shfl_xor_sync(0xffffffffu, sum, 1);
        sum += __shfl_xor_sync(0xffffffffu, sum, 2);
        sum += __shfl_xor_sync(0xffffffffu, sum, 4);
        sum += __shfl_xor_sync(0xffffffffu, sum, 8);
        if (c == 0) rs[row] = 1.0f / sum;
    }
    __syncthreads();

    // prefetch V tile 0 (overlaps the attn gmem write below)
    load_kv(0, 0);
    CP_COMMIT();

    // ---- write normalized attention ----
    {
        float* ap = out_attn + ((size_t)(n * BB + b)) * SS * SS + (size_t)s0 * SS;
        #pragma unroll
        for (int it = 0; it < 16; it++) {
            int idx = tid + it * 512;
            int r = idx >> 8;
            int c4 = (idx & 255) << 2;
            float4 v = *(const float4*)&scores[r * SCSTR + c4];
            float iv = rs[r];
            v.x *= iv; v.y *= iv; v.z *= iv; v.w *= iv;
            *(float4*)&ap[(size_t)r * SS + c4] = v;
        }
    }

    // ---- P @ V: warps 2m x 8n (16q x 8h each); P fp32 from scores,
    //      register hi/lo split; V dbuf ----
    const int wm = w >> 3, wn = w & 7;
    float pacc[4] = {};
    const int qr = wm * 16 + (lane >> 2);
    const int kcl = (lane & 3) * 2;
    #pragma unroll 1
    for (int jt = 0; jt < 8; jt++) {
        if (jt < 7) {
            load_kv((jt + 1) & 1, jt + 1);
            CP_COMMIT();
            CP_WAIT1();
        } else {
            CP_WAIT0();
        }
        __syncthreads();
        const uint32_t vbase = sb + A_KB + (jt & 1) * A_KBUF;

        #pragma unroll
        for (int ks = 0; ks < 8; ks++) {
            const int kc = jt * 128 + ks * 16 + kcl;
            float2 p00 = *(const float2*)&scores[qr * SCSTR + kc];
            float2 p10 = *(const float2*)&scores[(qr + 8) * SCSTR + kc];
            float2 p01 = *(const float2*)&scores[qr * SCSTR + kc + 8];
            float2 p11 = *(const float2*)&scores[(qr + 8) * SCSTR + kc + 8];
            unsigned ph4[4], pl4[4];
            split2(p00.x, p00.y, ph4[0], pl4[0]);
            split2(p10.x, p10.y, ph4[1], pl4[1]);
            split2(p01.x, p01.y, ph4[2], pl4[2]);
            split2(p11.x, p11.y, ph4[3], pl4[3]);

            unsigned vh[2], vl[2];
            uint32_t vb = vbase + (ks * 16 + (lane & 15)) * 144 + wn * 16;
            ldsm2t(vh, vb);
            ldsm2t(vl, vb + 18432);

            mma_bf16(pacc, ph4[0],ph4[1],ph4[2],ph4[3], vh[0], vh[1]);
            mma_bf16(pacc, ph4[0],ph4[1],ph4[2],ph4[3], vl[0], vl[1]);
            mma_bf16(pacc, pl4[0],pl4[1],pl4[2],pl4[3], vh[0], vh[1]);
        }
        __syncthreads();
    }

    // ---- epilogue: scale by 1/rowsum, write outh bf16 hi/lo ----
    {
        float iv0 = rs[qr], iv1 = rs[qr + 8];
        int cc = colbase + wn * 8 + 2 * (lane & 3);
        size_t go = (rowbase + s0 + qr) * 1024 + cc;
        unsigned h0, l0, h1, l1;
        split2(pacc[0] * iv0, pacc[1] * iv0, h0, l0);
        split2(pacc[2] * iv1, pacc[3] * iv1, h1, l1);
        *(unsigned*)(OHI + go) = h0;
        *(unsigned*)(OLO + go) = l0;
        *(unsigned*)(OHI + go + 8 * 1024) = h1;
        *(unsigned*)(OLO + go + 8 * 1024) = l1;
    }
}

// ---------------------------------------------------------------------------
// Layernorm per row of 1024
// ---------------------------------------------------------------------------
__global__ __launch_bounds__(256) void ln_kernel(float* __restrict__ y,
                                                 const float* __restrict__ g,
                                                 const float* __restrict__ bfn) {
    const int r = blockIdx.x;
    const int tid = threadIdx.x;
    const int lane = tid & 31, wid = tid >> 5;
    __shared__ float red1[8];
    __shared__ float red2[8];
    __shared__ float sh_mu, sh_rstd;

    float4 v = *(const float4*)&g_ypre[r * 1024 + tid * 4];
    float s = v.x + v.y + v.z + v.w;
    #pragma unroll
    for (int o = 16; o > 0; o >>= 1) s += __shfl_xor_sync(0xffffffffu, s, o);
    if (lane == 0) red1[wid] = s;
    __syncthreads();
    if (tid == 0) {
        float t = 0.f;
        #pragma unroll
        for (int i = 0; i < 8; i++) t += red1[i];
        sh_mu = t * (1.0f / 1024.0f);
    }
    __syncthreads();
    float mu = sh_mu;
    float dx = v.x - mu, dy = v.y - mu, dz = v.z - mu, dw = v.w - mu;
    float sq = dx * dx + dy * dy + dz * dz + dw * dw;
    #pragma unroll
    for (int o = 16; o > 0; o >>= 1) sq += __shfl_xor_sync(0xffffffffu, sq, o);
    if (lane == 0) red2[wid] = sq;
    __syncthreads();
    if (tid == 0) {
        float t = 0.f;
        #pragma unroll
        for (int i = 0; i < 8; i++) t += red2[i];
        sh_rstd = rsqrtf(t * (1.0f / 1024.0f) + 1e-5f);
    }
    __syncthreads();
    float rstd = sh_rstd;
    float4 gv = *(const float4*)&g[tid * 4];
    float4 bv = *(const float4*)&bfn[tid * 4];
    float4 o;
    o.x = dx * rstd * gv.x + bv.x;
    o.y = dy * rstd * gv.y + bv.y;
    o.z = dz * rstd * gv.z + bv.z;
    o.w = dw * rstd * gv.w + bv.w;
    *(float4*)&y[r * 1024 + tid * 4] = o;
}

// ---------------------------------------------------------------------------
extern "C" void kernel_launch(void* const* d_in, const int* in_sizes, int n_in,
                              void* d_out, int out_size) {
    const float* x   = (const float*)d_in[0];
    const float* w   = (const float*)d_in[1];
    const float* lw  = (const float*)d_in[2];
    const float* lb  = (const float*)d_in[3];
    const float* lng = (const float*)d_in[4];
    const float* lnb = (const float*)d_in[5];
    float* out = (float*)d_out;

    __nv_bfloat16 *xhi, *xlo, *wthi, *wtlo, *lwhi, *lwlo, *lhi, *llo, *ohhi, *ohlo;
    float *ypre;
    cudaGetSymbolAddress((void**)&xhi, g_xhi);   cudaGetSymbolAddress((void**)&xlo, g_xlo);
    cudaGetSymbolAddress((void**)&wthi, g_wThi); cudaGetSymbolAddress((void**)&wtlo, g_wTlo);
    cudaGetSymbolAddress((void**)&lwhi, g_lwhi); cudaGetSymbolAddress((void**)&lwlo, g_lwlo);
    cudaGetSymbolAddress((void**)&lhi, g_lhi);   cudaGetSymbolAddress((void**)&llo, g_llo);
    cudaGetSymbolAddress((void**)&ohhi, g_ohhi); cudaGetSymbolAddress((void**)&ohlo, g_ohlo);
    cudaGetSymbolAddress((void**)&ypre, g_ypre);

    cudaFuncSetAttribute(gemm_mma<0>, cudaFuncAttributeMaxDynamicSharedMemorySize, GSMEM);
    cudaFuncSetAttribute(gemm_mma<1>, cudaFuncAttributeMaxDynamicSharedMemorySize, GSMEM);
    cudaFuncSetAttribute(attn_kernel, cudaFuncAttributeMaxDynamicSharedMemorySize, ASMEM);

    // input splits
    split4_kernel<<<8192, 256>>>(x, xhi, xlo, MROWS * DD / 4);
    convw_kernel<<<4096, 256>>>(w);
    split4_kernel<<<1024, 256>>>(lw, lwhi, lwlo, DD * DD / 4);

    // head projection -> logits (bf16 hi/lo, concat layout)
    gemm_mma<0><<<dim3(64, 8), 256, GSMEM>>>(xhi, xlo, wthi, wtlo,
                                             lhi, llo, nullptr, nullptr, nullptr);
    // fused attention: writes attn matrix + outh (bf16 hi/lo)
    attn_kernel<<<dim3(32, 8, 16), 512, ASMEM>>>(lhi, llo, out + Y_SIZE, ohhi, ohlo);
    // output projection + residual + bias
    gemm_mma<1><<<dim3(64, 8), 256, GSMEM>>>(ohhi, ohlo, lwhi, lwlo,
                                             nullptr, nullptr, ypre, x, lb);
    // layernorm
    ln_kernel<<<MROWS, 256>>>(out, lng, lnb);
}